// round 7
// baseline (speedup 1.0000x reference)
#include <cuda_runtime.h>
#include <math.h>

// ---------------------------------------------------------------------------
// Problem shape (fixed): B=256, R=512, D=64, N=100000, E=3200000
// Strategy: never materialize M[N,R]. One streaming pass over edges with a
// shared-memory node-membership bitmap; counts only for the <=256 query
// entities; tiny fused MLP at the end.
// ---------------------------------------------------------------------------

#define R_MAX      512
#define B_MAX      256
#define NODE_WORDS 4096          // bitmap capacity: 131072 node ids
#define SLOT_CAP   131072

__device__ int      g_node_slot[SLOT_CAP];       // node -> min query index (valid only where bitmap set)
__device__ unsigned g_bitmap[NODE_WORDS];        // node membership bitmap
__device__ int      g_counts[B_MAX * R_MAX];     // per-(slot, relation) incident counts
__device__ int      g_relcnt[R_MAX];             // global relation histogram

// ---------------------------------------------------------------------------
// K1: clear bitmap + counts + relcnt (node_slot handled in k_scatter)
// ---------------------------------------------------------------------------
__global__ void k_init() {
    int i = blockIdx.x * blockDim.x + threadIdx.x;
    if (i < NODE_WORDS)      g_bitmap[i] = 0u;
    if (i < B_MAX * R_MAX)   g_counts[i] = 0;
    if (i < R_MAX)           g_relcnt[i] = 0;
}

// ---------------------------------------------------------------------------
// K2: single block. Seed node_slot ONLY at query entities, then dedup via
// atomicMin and set membership bitmap. Avoids initializing all 131072 slots.
// ---------------------------------------------------------------------------
__global__ void k_scatter(const int* __restrict__ query_entities, int B) {
    int b = threadIdx.x;
    int e = (b < B) ? query_entities[b] : -1;
    if (b < B) g_node_slot[e] = 0x7fffffff;
    __syncthreads();
    if (b < B) {
        atomicOr(&g_bitmap[e >> 5], 1u << (e & 31));
        atomicMin(&g_node_slot[e], b);
    }
}

// ---------------------------------------------------------------------------
// K3: streaming edge scan.
//  - shared histogram for rel_counts
//  - shared bitmap for membership test (avoids random global gathers)
//  - edge counted once per incident query endpoint; self-loop counted once
// ---------------------------------------------------------------------------
__global__ void __launch_bounds__(256) k_scan(const int* __restrict__ heads,
                                              const int* __restrict__ tails,
                                              const int* __restrict__ types,
                                              int E, int R) {
    __shared__ unsigned bm[NODE_WORDS];
    __shared__ int hist[R_MAX];
    for (int i = threadIdx.x; i < NODE_WORDS; i += blockDim.x) bm[i] = g_bitmap[i];
    for (int i = threadIdx.x; i < R_MAX;      i += blockDim.x) hist[i] = 0;
    __syncthreads();

    auto proc = [&](int hh, int tt, int rr) {
        atomicAdd(&hist[rr], 1);
        if ((bm[hh >> 5] >> (hh & 31)) & 1u)
            atomicAdd(&g_counts[__ldg(&g_node_slot[hh]) * R_MAX + rr], 1);
        if (hh != tt && ((bm[tt >> 5] >> (tt & 31)) & 1u))
            atomicAdd(&g_counts[__ldg(&g_node_slot[tt]) * R_MAX + rr], 1);
    };

    bool vec_ok = ((E & 3) == 0);   // tails/types ptrs 16B-aligned iff E % 4 == 0
    if (vec_ok) {
        int quads = E >> 2;
        const int4* h4 = (const int4*)heads;
        const int4* t4 = (const int4*)tails;
        const int4* r4 = (const int4*)types;
        for (int q = blockIdx.x * blockDim.x + threadIdx.x; q < quads;
             q += gridDim.x * blockDim.x) {
            int4 h = h4[q], t = t4[q], r = r4[q];
            proc(h.x, t.x, r.x);
            proc(h.y, t.y, r.y);
            proc(h.z, t.z, r.z);
            proc(h.w, t.w, r.w);
        }
    } else {
        for (int e = blockIdx.x * blockDim.x + threadIdx.x; e < E;
             e += gridDim.x * blockDim.x) {
            proc(heads[e], tails[e], types[e]);
        }
    }

    __syncthreads();
    for (int i = threadIdx.x; i < R; i += blockDim.x) {
        int v = hist[i];
        if (v) atomicAdd(&g_relcnt[i], v);
    }
}

// ---------------------------------------------------------------------------
// K4: per-query gate. One block of D(=64) threads per query.
//   x = [qrel_emb(D), entity_emb(D), freq, degn, freq, density]
//   gate = sigmoid(relu(relu(relu(x W1+b1) W2+b2) W3+b3) W4 + b4)
// ---------------------------------------------------------------------------
__global__ void __launch_bounds__(64) k_gate(const float* __restrict__ rel_emb,
                                             const int* __restrict__ query_rels,
                                             const int* __restrict__ query_entities,
                                             const float* __restrict__ W1, const float* __restrict__ b1,
                                             const float* __restrict__ W2, const float* __restrict__ b2,
                                             const float* __restrict__ W3, const float* __restrict__ b3,
                                             const float* __restrict__ W4, const float* __restrict__ b4,
                                             float* __restrict__ out,
                                             int R, int D, int E,
                                             const int* __restrict__ num_nodes_ptr,
                                             int n_default) {
    int b = blockIdx.x;
    int j = threadIdx.x;                 // 0 .. D-1
    int lane = j & 31;
    int wrp  = j >> 5;

    __shared__ float s_cnt[R_MAX];
    __shared__ float s_x[2 * 64 + 4];
    __shared__ float s_h1[64];
    __shared__ float s_h2[32];
    __shared__ float s_g[16];
    __shared__ float s_wsum[2];
    __shared__ float s_deg;

    int qe = query_entities[b];
    int qr = query_rels[b];
    int slot = g_node_slot[qe];          // always valid: b itself wrote it
    const int* cnt_row = &g_counts[slot * R_MAX];

    float part = 0.f;
    for (int r = j; r < R; r += blockDim.x) {
        float c = (float)cnt_row[r];
        s_cnt[r] = c;
        part += c;
    }
    // warp-shuffle reduce, then combine two warps
    #pragma unroll
    for (int off = 16; off > 0; off >>= 1)
        part += __shfl_xor_sync(0xffffffffu, part, off);
    if (lane == 0) s_wsum[wrp] = part;
    __syncthreads();
    if (j == 0) s_deg = s_wsum[0] + s_wsum[1];
    __syncthreads();
    float deg = s_deg;
    float inv = 1.0f / fmaxf(deg, 1.0f);

    // entity embedding (dim j): skip zero-count relations (block-uniform branch)
    const float* emb = rel_emb + (size_t)b * (size_t)R * (size_t)D;
    float acc = 0.f;
    for (int r = 0; r < R; r++) {
        float c = s_cnt[r];
        if (c != 0.f) acc += c * emb[r * D + j];
    }
    s_x[j]     = emb[qr * D + j];        // query relation embedding
    s_x[D + j] = acc * inv;              // masked-mean entity embedding
    if (j == 0) {
        float Ef   = (float)E;
        float freq = fminf((float)g_relcnt[qr] / Ef, 1.0f);
        float degn = fminf(deg / Ef, 1.0f);
        int   N    = num_nodes_ptr ? *num_nodes_ptr : n_default;
        float density = fminf(Ef / ((float)N * (float)N), 1.0f);
        s_x[2 * D + 0] = freq;
        s_x[2 * D + 1] = degn;
        s_x[2 * D + 2] = freq;
        s_x[2 * D + 3] = density;
    }
    __syncthreads();

    // layer 1: (2D+4) -> D ; W1 row-major [din, D], coalesced across j
    int din = 2 * D + 4;
    float a1 = b1[j];
    #pragma unroll 4
    for (int i = 0; i < din; i++) a1 += s_x[i] * W1[i * D + j];
    s_h1[j] = fmaxf(a1, 0.f);
    __syncthreads();

    int H2 = D / 2;
    if (j < H2) {
        float a2 = b2[j];
        #pragma unroll 8
        for (int i = 0; i < D; i++) a2 += s_h1[i] * W2[i * H2 + j];
        s_h2[j] = fmaxf(a2, 0.f);
    }
    __syncthreads();

    int H3 = D / 4;
    if (j < H3) {
        float a3 = b3[j];
        #pragma unroll 8
        for (int i = 0; i < H2; i++) a3 += s_h2[i] * W3[i * H3 + j];
        s_g[j] = fmaxf(a3, 0.f);
    }
    __syncthreads();

    if (j == 0) {
        float z = b4[0];
        #pragma unroll
        for (int i = 0; i < H3; i++) z += s_g[i] * W4[i];
        out[b] = 1.0f / (1.0f + expf(-z));
    }
}

// ---------------------------------------------------------------------------
// Host launcher (graph-capturable: kernel launches only, default stream)
// ---------------------------------------------------------------------------
extern "C" void kernel_launch(void* const* d_in, const int* in_sizes, int n_in,
                              void* d_out, int out_size) {
    const float* rel_emb    = (const float*)d_in[0];
    const int*   qrels      = (const int*)d_in[1];
    const int*   qents      = (const int*)d_in[2];
    const int*   edge_index = (const int*)d_in[3];
    const int*   edge_type  = (const int*)d_in[4];

    int B = in_sizes[1];
    int E = in_sizes[4];

    // Scalars (num_nodes, num_relations) may or may not appear as size-1
    // inputs at indices 5.. — skip any size-1 entries to find W1 (first
    // large tensor). b4 (also size 1) sits safely AFTER W1.
    int i = 5;
    const int* num_nodes_ptr = nullptr;
    while (i < n_in && in_sizes[i] == 1) {
        if (num_nodes_ptr == nullptr) num_nodes_ptr = (const int*)d_in[i];
        i++;
    }
    const float* W1 = (const float*)d_in[i + 0];
    const float* b1 = (const float*)d_in[i + 1];
    const float* W2 = (const float*)d_in[i + 2];
    const float* b2 = (const float*)d_in[i + 3];
    const float* W3 = (const float*)d_in[i + 4];
    const float* b3 = (const float*)d_in[i + 5];
    const float* W4 = (const float*)d_in[i + 6];
    const float* b4 = (const float*)d_in[i + 7];

    int D = in_sizes[i + 1];             // b1 has D elements
    int R = in_sizes[0] / (B * D);

    k_init<<<(B_MAX * R_MAX + 255) / 256, 256>>>();
    k_scatter<<<1, 256>>>(qents, B);
    k_scan<<<1184, 256>>>(edge_index, edge_index + E, edge_type, E, R);
    k_gate<<<B, D>>>(rel_emb, qrels, qents,
                     W1, b1, W2, b2, W3, b3, W4, b4,
                     (float*)d_out, R, D, E, num_nodes_ptr, 100000);
}

// round 8
// speedup vs baseline: 1.3954x; 1.3954x over previous
#include <cuda_runtime.h>
#include <math.h>

// ---------------------------------------------------------------------------
// Problem shape (fixed): B=256, R=512, D=64, N=100000, E=3200000
// ---------------------------------------------------------------------------

#define R_MAX      512
#define B_MAX      256
#define NODE_WORDS 4096          // bitmap capacity: 131072 node ids
#define SLOT_CAP   131072

__device__ int      g_node_slot[SLOT_CAP];
__device__ unsigned g_bitmap[NODE_WORDS];
__device__ int      g_counts[B_MAX * R_MAX];
__device__ int      g_relcnt[R_MAX];

// ---------------------------------------------------------------------------
// K1: clear bitmap + counts + relcnt (node_slot handled in k_scatter)
// ---------------------------------------------------------------------------
__global__ void k_init() {
    int i = blockIdx.x * blockDim.x + threadIdx.x;
    if (i < NODE_WORDS)      g_bitmap[i] = 0u;
    if (i < B_MAX * R_MAX)   g_counts[i] = 0;
    if (i < R_MAX)           g_relcnt[i] = 0;
}

// ---------------------------------------------------------------------------
// K2: single block. Seed node_slot ONLY at query entities, dedup via atomicMin.
// ---------------------------------------------------------------------------
__global__ void k_scatter(const int* __restrict__ query_entities, int B) {
    int b = threadIdx.x;
    int e = (b < B) ? query_entities[b] : -1;
    if (b < B) g_node_slot[e] = 0x7fffffff;
    __syncthreads();
    if (b < B) {
        atomicOr(&g_bitmap[e >> 5], 1u << (e & 31));
        atomicMin(&g_node_slot[e], b);
    }
}

// ---------------------------------------------------------------------------
// K3: streaming edge scan (unchanged — presumed DRAM-bound ~6us).
// ---------------------------------------------------------------------------
__global__ void __launch_bounds__(256) k_scan(const int* __restrict__ heads,
                                              const int* __restrict__ tails,
                                              const int* __restrict__ types,
                                              int E, int R) {
    __shared__ unsigned bm[NODE_WORDS];
    __shared__ int hist[R_MAX];
    for (int i = threadIdx.x; i < NODE_WORDS; i += blockDim.x) bm[i] = g_bitmap[i];
    for (int i = threadIdx.x; i < R_MAX;      i += blockDim.x) hist[i] = 0;
    __syncthreads();

    auto proc = [&](int hh, int tt, int rr) {
        atomicAdd(&hist[rr], 1);
        if ((bm[hh >> 5] >> (hh & 31)) & 1u)
            atomicAdd(&g_counts[__ldg(&g_node_slot[hh]) * R_MAX + rr], 1);
        if (hh != tt && ((bm[tt >> 5] >> (tt & 31)) & 1u))
            atomicAdd(&g_counts[__ldg(&g_node_slot[tt]) * R_MAX + rr], 1);
    };

    bool vec_ok = ((E & 3) == 0);
    if (vec_ok) {
        int quads = E >> 2;
        const int4* h4 = (const int4*)heads;
        const int4* t4 = (const int4*)tails;
        const int4* r4 = (const int4*)types;
        for (int q = blockIdx.x * blockDim.x + threadIdx.x; q < quads;
             q += gridDim.x * blockDim.x) {
            int4 h = h4[q], t = t4[q], r = r4[q];
            proc(h.x, t.x, r.x);
            proc(h.y, t.y, r.y);
            proc(h.z, t.z, r.z);
            proc(h.w, t.w, r.w);
        }
    } else {
        for (int e = blockIdx.x * blockDim.x + threadIdx.x; e < E;
             e += gridDim.x * blockDim.x) {
            proc(heads[e], tails[e], types[e]);
        }
    }

    __syncthreads();
    for (int i = threadIdx.x; i < R; i += blockDim.x) {
        int v = hist[i];
        if (v) atomicAdd(&g_relcnt[i], v);
    }
}

// ---------------------------------------------------------------------------
// K4 (REDESIGNED): 256 threads/block, one block per query.
//  Dense coalesced reduction over ALL 512 relations (no branch): the 128KB
//  per-block emb slice streams at full DRAM BW; zero-count rows are free FMAs.
//  thread t: j = t&63 (dim), rg = t>>6 (4-way split of R). 128 independent
//  coalesced loads per thread, unroll 4 -> high MLP. SMEM combine, then MLP.
// ---------------------------------------------------------------------------
__global__ void __launch_bounds__(256) k_gate(const float* __restrict__ rel_emb,
                                              const int* __restrict__ query_rels,
                                              const int* __restrict__ query_entities,
                                              const float* __restrict__ W1, const float* __restrict__ b1,
                                              const float* __restrict__ W2, const float* __restrict__ b2,
                                              const float* __restrict__ W3, const float* __restrict__ b3,
                                              const float* __restrict__ W4, const float* __restrict__ b4,
                                              float* __restrict__ out,
                                              int R, int D, int E,
                                              const int* __restrict__ num_nodes_ptr,
                                              int n_default) {
    int b = blockIdx.x;
    int t = threadIdx.x;                 // 0..255
    int j = t & 63;                      // embedding dim
    int rg = t >> 6;                     // 0..3 relation-group

    __shared__ float s_cnt[R_MAX];
    __shared__ float s_part[4][64];
    __shared__ float s_x[2 * 64 + 4];
    __shared__ float s_h1[64];
    __shared__ float s_h2[32];
    __shared__ float s_g[16];
    __shared__ float s_wsum[8];
    __shared__ float s_deg;

    int qe = query_entities[b];
    int qr = query_rels[b];
    int slot = g_node_slot[qe];          // always valid: b itself wrote it
    const int* cnt_row = &g_counts[slot * R_MAX];

    // load counts (2 per thread) + degree reduction across 256 threads
    float part = 0.f;
    for (int r = t; r < R; r += 256) {
        float c = (float)cnt_row[r];
        s_cnt[r] = c;
        part += c;
    }
    #pragma unroll
    for (int off = 16; off > 0; off >>= 1)
        part += __shfl_xor_sync(0xffffffffu, part, off);
    if ((t & 31) == 0) s_wsum[t >> 5] = part;
    __syncthreads();
    if (t == 0) {
        float d = 0.f;
        #pragma unroll
        for (int w = 0; w < 8; w++) d += s_wsum[w];
        s_deg = d;
    }
    __syncthreads();
    float deg = s_deg;
    float inv = 1.0f / fmaxf(deg, 1.0f);

    // dense coalesced weighted sum: acc_j = sum_r cnt[r]*emb[r][j]
    const float* emb = rel_emb + (size_t)b * (size_t)R * (size_t)D;
    float acc = 0.f;
    #pragma unroll 4
    for (int r = rg; r < R; r += 4) {
        acc += s_cnt[r] * __ldg(&emb[r * 64 + j]);
    }
    s_part[rg][j] = acc;
    __syncthreads();

    if (t < 64) {
        float a = s_part[0][j] + s_part[1][j] + s_part[2][j] + s_part[3][j];
        s_x[j]      = __ldg(&emb[qr * 64 + j]);   // query relation embedding
        s_x[64 + j] = a * inv;                    // masked-mean entity embedding
    }
    if (t == 0) {
        float Ef   = (float)E;
        float freq = fminf((float)g_relcnt[qr] / Ef, 1.0f);
        float degn = fminf(deg / Ef, 1.0f);
        int   N    = num_nodes_ptr ? *num_nodes_ptr : n_default;
        float density = fminf(Ef / ((float)N * (float)N), 1.0f);
        s_x[128 + 0] = freq;
        s_x[128 + 1] = degn;
        s_x[128 + 2] = freq;
        s_x[128 + 3] = density;
    }
    __syncthreads();

    // layer 1: 132 -> 64 ; W1 row-major [132, 64], coalesced across j
    if (t < 64) {
        float a1 = b1[j];
        #pragma unroll 4
        for (int i = 0; i < 132; i++) a1 += s_x[i] * W1[i * 64 + j];
        s_h1[j] = fmaxf(a1, 0.f);
    }
    __syncthreads();

    if (t < 32) {
        float a2 = b2[t];
        #pragma unroll 8
        for (int i = 0; i < 64; i++) a2 += s_h1[i] * W2[i * 32 + t];
        s_h2[t] = fmaxf(a2, 0.f);
    }
    __syncthreads();

    if (t < 16) {
        float a3 = b3[t];
        #pragma unroll 8
        for (int i = 0; i < 32; i++) a3 += s_h2[i] * W3[i * 16 + t];
        s_g[t] = fmaxf(a3, 0.f);
    }
    __syncthreads();

    if (t == 0) {
        float z = b4[0];
        #pragma unroll
        for (int i = 0; i < 16; i++) z += s_g[i] * W4[i];
        out[b] = 1.0f / (1.0f + expf(-z));
    }
}

// ---------------------------------------------------------------------------
// Host launcher (graph-capturable: kernel launches only, default stream)
// ---------------------------------------------------------------------------
extern "C" void kernel_launch(void* const* d_in, const int* in_sizes, int n_in,
                              void* d_out, int out_size) {
    const float* rel_emb    = (const float*)d_in[0];
    const int*   qrels      = (const int*)d_in[1];
    const int*   qents      = (const int*)d_in[2];
    const int*   edge_index = (const int*)d_in[3];
    const int*   edge_type  = (const int*)d_in[4];

    int B = in_sizes[1];
    int E = in_sizes[4];

    int i = 5;
    const int* num_nodes_ptr = nullptr;
    while (i < n_in && in_sizes[i] == 1) {
        if (num_nodes_ptr == nullptr) num_nodes_ptr = (const int*)d_in[i];
        i++;
    }
    const float* W1 = (const float*)d_in[i + 0];
    const float* b1 = (const float*)d_in[i + 1];
    const float* W2 = (const float*)d_in[i + 2];
    const float* b2 = (const float*)d_in[i + 3];
    const float* W3 = (const float*)d_in[i + 4];
    const float* b3 = (const float*)d_in[i + 5];
    const float* W4 = (const float*)d_in[i + 6];
    const float* b4 = (const float*)d_in[i + 7];

    int D = in_sizes[i + 1];             // b1 has D elements (64)
    int R = in_sizes[0] / (B * D);       // 512

    k_init<<<(B_MAX * R_MAX + 255) / 256, 256>>>();
    k_scatter<<<1, 256>>>(qents, B);
    k_scan<<<1184, 256>>>(edge_index, edge_index + E, edge_type, E, R);
    k_gate<<<B, 256>>>(rel_emb, qrels, qents,
                       W1, b1, W2, b2, W3, b3, W4, b4,
                       (float*)d_out, R, D, E, num_nodes_ptr, 100000);
}

// round 9
// speedup vs baseline: 1.6250x; 1.1646x over previous
#include <cuda_runtime.h>
#include <math.h>

// ---------------------------------------------------------------------------
// Problem shape (fixed): B=256, R=512, D=64, N=100000, E=3200000
// ---------------------------------------------------------------------------

#define R_MAX      512
#define B_MAX      256
#define NODE_WORDS 4096          // bitmap capacity: 131072 node ids
#define SLOT_CAP   131072

__device__ int      g_node_slot[SLOT_CAP];
__device__ unsigned g_bitmap[NODE_WORDS];
__device__ int      g_counts[B_MAX * R_MAX];
__device__ int      g_relcnt[R_MAX];

// ---------------------------------------------------------------------------
// K1: clear bitmap + counts + relcnt (node_slot handled in k_scatter)
// ---------------------------------------------------------------------------
__global__ void k_init() {
    int i = blockIdx.x * blockDim.x + threadIdx.x;
    if (i < NODE_WORDS)      g_bitmap[i] = 0u;
    if (i < B_MAX * R_MAX)   g_counts[i] = 0;
    if (i < R_MAX)           g_relcnt[i] = 0;
}

// ---------------------------------------------------------------------------
// K2: single block. Seed node_slot ONLY at query entities, dedup via atomicMin.
// ---------------------------------------------------------------------------
__global__ void k_scatter(const int* __restrict__ query_entities, int B) {
    int b = threadIdx.x;
    int e = (b < B) ? query_entities[b] : -1;
    if (b < B) g_node_slot[e] = 0x7fffffff;
    __syncthreads();
    if (b < B) {
        atomicOr(&g_bitmap[e >> 5], 1u << (e & 31));
        atomicMin(&g_node_slot[e], b);
    }
}

// ---------------------------------------------------------------------------
// K3: streaming edge scan (fast per R8 profile — k_gate dominated).
// ---------------------------------------------------------------------------
__global__ void __launch_bounds__(256) k_scan(const int* __restrict__ heads,
                                              const int* __restrict__ tails,
                                              const int* __restrict__ types,
                                              int E, int R) {
    __shared__ unsigned bm[NODE_WORDS];
    __shared__ int hist[R_MAX];
    for (int i = threadIdx.x; i < NODE_WORDS; i += blockDim.x) bm[i] = g_bitmap[i];
    for (int i = threadIdx.x; i < R_MAX;      i += blockDim.x) hist[i] = 0;
    __syncthreads();

    auto proc = [&](int hh, int tt, int rr) {
        atomicAdd(&hist[rr], 1);
        if ((bm[hh >> 5] >> (hh & 31)) & 1u)
            atomicAdd(&g_counts[__ldg(&g_node_slot[hh]) * R_MAX + rr], 1);
        if (hh != tt && ((bm[tt >> 5] >> (tt & 31)) & 1u))
            atomicAdd(&g_counts[__ldg(&g_node_slot[tt]) * R_MAX + rr], 1);
    };

    bool vec_ok = ((E & 3) == 0);
    if (vec_ok) {
        int quads = E >> 2;
        const int4* h4 = (const int4*)heads;
        const int4* t4 = (const int4*)tails;
        const int4* r4 = (const int4*)types;
        for (int q = blockIdx.x * blockDim.x + threadIdx.x; q < quads;
             q += gridDim.x * blockDim.x) {
            int4 h = h4[q], t = t4[q], r = r4[q];
            proc(h.x, t.x, r.x);
            proc(h.y, t.y, r.y);
            proc(h.z, t.z, r.z);
            proc(h.w, t.w, r.w);
        }
    } else {
        for (int e = blockIdx.x * blockDim.x + threadIdx.x; e < E;
             e += gridDim.x * blockDim.x) {
            proc(heads[e], tails[e], types[e]);
        }
    }

    __syncthreads();
    for (int i = threadIdx.x; i < R; i += blockDim.x) {
        int v = hist[i];
        if (v) atomicAdd(&g_relcnt[i], v);
    }
}

// ---------------------------------------------------------------------------
// K4: one block (256 thr) per query.
//  1) load counts, deterministic warp-ballot compaction of ~64 nonzero
//     relations (ordered by r — bitwise reproducible, no atomics)
//  2) parallel gather: thread t -> dim j=t&63, row-group rg=t>>6; each thread
//     does ~nnz/4 independent coalesced 256B-row loads (high MLP, no branch)
//  3) tiny fused MLP
// ---------------------------------------------------------------------------
__global__ void __launch_bounds__(256) k_gate(const float* __restrict__ rel_emb,
                                              const int* __restrict__ query_rels,
                                              const int* __restrict__ query_entities,
                                              const float* __restrict__ W1, const float* __restrict__ b1,
                                              const float* __restrict__ W2, const float* __restrict__ b2,
                                              const float* __restrict__ W3, const float* __restrict__ b3,
                                              const float* __restrict__ W4, const float* __restrict__ b4,
                                              float* __restrict__ out,
                                              int R, int D, int E,
                                              const int* __restrict__ num_nodes_ptr,
                                              int n_default) {
    int b = blockIdx.x;
    int t = threadIdx.x;                 // 0..255
    int lane = t & 31;
    int wid  = t >> 5;                   // 0..7
    int j  = t & 63;                     // embedding dim
    int rg = t >> 6;                     // 0..3 row-group

    __shared__ float s_val[R_MAX];
    __shared__ int   s_idx[R_MAX];
    __shared__ int   s_wcnt[8], s_woff[8];
    __shared__ int   s_nnz;
    __shared__ float s_part[4][64];
    __shared__ float s_x[2 * 64 + 4];
    __shared__ float s_h1[64];
    __shared__ float s_h2[32];
    __shared__ float s_g[16];
    __shared__ float s_wsum[8];
    __shared__ float s_deg;

    int qe = query_entities[b];
    int qr = query_rels[b];
    int slot = g_node_slot[qe];
    const int* cnt_row = &g_counts[slot * R_MAX];

    // load both halves of the count row (coalesced)
    float c0 = (float)cnt_row[t];
    float c1 = (float)cnt_row[t + 256];

    // degree reduction (fixed order -> deterministic)
    float part = c0 + c1;
    #pragma unroll
    for (int off = 16; off > 0; off >>= 1)
        part += __shfl_xor_sync(0xffffffffu, part, off);
    if (lane == 0) s_wsum[wid] = part;

    // ---- deterministic compaction, round 0: r = t (0..255) ----
    bool p0 = (c0 != 0.f);
    unsigned m0 = __ballot_sync(0xffffffffu, p0);
    int wp0 = __popc(m0 & ((1u << lane) - 1u));
    if (lane == 0) s_wcnt[wid] = __popc(m0);
    __syncthreads();
    if (t == 0) {
        int o = 0;
        #pragma unroll
        for (int w = 0; w < 8; w++) { s_woff[w] = o; o += s_wcnt[w]; }
        s_nnz = o;
        float d = 0.f;
        #pragma unroll
        for (int w = 0; w < 8; w++) d += s_wsum[w];
        s_deg = d;
    }
    __syncthreads();
    if (p0) { int p = s_woff[wid] + wp0; s_idx[p] = t; s_val[p] = c0; }
    int base0 = s_nnz;
    __syncthreads();

    // ---- round 1: r = 256 + t ----
    bool p1 = (c1 != 0.f);
    unsigned m1 = __ballot_sync(0xffffffffu, p1);
    int wp1 = __popc(m1 & ((1u << lane) - 1u));
    if (lane == 0) s_wcnt[wid] = __popc(m1);
    __syncthreads();
    if (t == 0) {
        int o = base0;
        #pragma unroll
        for (int w = 0; w < 8; w++) { s_woff[w] = o; o += s_wcnt[w]; }
        s_nnz = o;
    }
    __syncthreads();
    if (p1) { int p = s_woff[wid] + wp1; s_idx[p] = 256 + t; s_val[p] = c1; }
    __syncthreads();

    int nnz = s_nnz;
    float deg = s_deg;
    float inv = 1.0f / fmaxf(deg, 1.0f);

    // ---- sparse parallel gather: acc_j = sum_i val[i]*emb[idx[i]][j] ----
    const float* emb = rel_emb + (size_t)b * (size_t)R * 64;
    float acc = 0.f;
    #pragma unroll 4
    for (int i = rg; i < nnz; i += 4)
        acc += s_val[i] * __ldg(&emb[s_idx[i] * 64 + j]);
    s_part[rg][j] = acc;
    __syncthreads();

    if (t < 64) {
        float a = s_part[0][j] + s_part[1][j] + s_part[2][j] + s_part[3][j];
        s_x[j]      = __ldg(&emb[qr * 64 + j]);   // query relation embedding
        s_x[64 + j] = a * inv;                    // masked-mean entity embedding
    }
    if (t == 0) {
        float Ef   = (float)E;
        float freq = fminf((float)g_relcnt[qr] / Ef, 1.0f);
        float degn = fminf(deg / Ef, 1.0f);
        int   N    = num_nodes_ptr ? *num_nodes_ptr : n_default;
        float density = fminf(Ef / ((float)N * (float)N), 1.0f);
        s_x[128 + 0] = freq;
        s_x[128 + 1] = degn;
        s_x[128 + 2] = freq;
        s_x[128 + 3] = density;
    }
    __syncthreads();

    // ---- MLP: 132 -> 64 -> 32 -> 16 -> 1 ----
    if (t < 64) {
        float a1 = b1[j];
        #pragma unroll 4
        for (int i = 0; i < 132; i++) a1 += s_x[i] * W1[i * 64 + j];
        s_h1[j] = fmaxf(a1, 0.f);
    }
    __syncthreads();

    if (t < 32) {
        float a2 = b2[t];
        #pragma unroll 8
        for (int i = 0; i < 64; i++) a2 += s_h1[i] * W2[i * 32 + t];
        s_h2[t] = fmaxf(a2, 0.f);
    }
    __syncthreads();

    if (t < 16) {
        float a3 = b3[t];
        #pragma unroll 8
        for (int i = 0; i < 32; i++) a3 += s_h2[i] * W3[i * 16 + t];
        s_g[t] = fmaxf(a3, 0.f);
    }
    __syncthreads();

    if (t == 0) {
        float z = b4[0];
        #pragma unroll
        for (int i = 0; i < 16; i++) z += s_g[i] * W4[i];
        out[b] = 1.0f / (1.0f + expf(-z));
    }
}

// ---------------------------------------------------------------------------
// Host launcher (graph-capturable: kernel launches only, default stream)
// ---------------------------------------------------------------------------
extern "C" void kernel_launch(void* const* d_in, const int* in_sizes, int n_in,
                              void* d_out, int out_size) {
    const float* rel_emb    = (const float*)d_in[0];
    const int*   qrels      = (const int*)d_in[1];
    const int*   qents      = (const int*)d_in[2];
    const int*   edge_index = (const int*)d_in[3];
    const int*   edge_type  = (const int*)d_in[4];

    int B = in_sizes[1];
    int E = in_sizes[4];

    int i = 5;
    const int* num_nodes_ptr = nullptr;
    while (i < n_in && in_sizes[i] == 1) {
        if (num_nodes_ptr == nullptr) num_nodes_ptr = (const int*)d_in[i];
        i++;
    }
    const float* W1 = (const float*)d_in[i + 0];
    const float* b1 = (const float*)d_in[i + 1];
    const float* W2 = (const float*)d_in[i + 2];
    const float* b2 = (const float*)d_in[i + 3];
    const float* W3 = (const float*)d_in[i + 4];
    const float* b3 = (const float*)d_in[i + 5];
    const float* W4 = (const float*)d_in[i + 6];
    const float* b4 = (const float*)d_in[i + 7];

    int D = in_sizes[i + 1];             // 64
    int R = in_sizes[0] / (B * D);       // 512

    k_init<<<(B_MAX * R_MAX + 255) / 256, 256>>>();
    k_scatter<<<1, 256>>>(qents, B);
    k_scan<<<1184, 256>>>(edge_index, edge_index + E, edge_type, E, R);
    k_gate<<<B, 256>>>(rel_emb, qrels, qents,
                       W1, b1, W2, b2, W3, b3, W4, b4,
                       (float*)d_out, R, D, E, num_nodes_ptr, 100000);
}

// round 14
// speedup vs baseline: 1.9641x; 1.2087x over previous
#include <cuda_runtime.h>
#include <math.h>

// ---------------------------------------------------------------------------
// Problem shape (fixed): B=256, R=512, D=64, N=100000, E=3200000
// ---------------------------------------------------------------------------

#define R_MAX      512
#define B_MAX      256
#define NODE_WORDS 4096          // bitmap capacity: 131072 node ids
#define SLOT_CAP   131072

__device__ int      g_node_slot[SLOT_CAP];
__device__ unsigned g_bitmap[NODE_WORDS];
__device__ int      g_counts[B_MAX * R_MAX];
__device__ int      g_relcnt[R_MAX];

// ---------------------------------------------------------------------------
// K1 (fused init+scatter): block 0 clears bitmap/relcnt then scatters query
// entities; blocks 1..512 clear the 512KB counts array.
// ---------------------------------------------------------------------------
__global__ void k_init_scatter(const int* __restrict__ query_entities, int B) {
    if (blockIdx.x == 0) {
        for (int i = threadIdx.x; i < NODE_WORDS; i += 256) g_bitmap[i] = 0u;
        for (int i = threadIdx.x; i < R_MAX;      i += 256) g_relcnt[i] = 0;
        __syncthreads();
        int b = threadIdx.x;
        int e = (b < B) ? query_entities[b] : -1;
        if (b < B) g_node_slot[e] = 0x7fffffff;
        __syncthreads();
        if (b < B) {
            atomicOr(&g_bitmap[e >> 5], 1u << (e & 31));
            atomicMin(&g_node_slot[e], b);
        }
    } else {
        int i = (blockIdx.x - 1) * 256 + threadIdx.x;
        if (i < B_MAX * R_MAX) g_counts[i] = 0;
    }
}

// ---------------------------------------------------------------------------
// K3: streaming edge scan (DRAM-bound, unchanged)
// ---------------------------------------------------------------------------
__global__ void __launch_bounds__(256) k_scan(const int* __restrict__ heads,
                                              const int* __restrict__ tails,
                                              const int* __restrict__ types,
                                              int E, int R) {
    __shared__ unsigned bm[NODE_WORDS];
    __shared__ int hist[R_MAX];
    for (int i = threadIdx.x; i < NODE_WORDS; i += blockDim.x) bm[i] = g_bitmap[i];
    for (int i = threadIdx.x; i < R_MAX;      i += blockDim.x) hist[i] = 0;
    __syncthreads();

    auto proc = [&](int hh, int tt, int rr) {
        atomicAdd(&hist[rr], 1);
        if ((bm[hh >> 5] >> (hh & 31)) & 1u)
            atomicAdd(&g_counts[__ldg(&g_node_slot[hh]) * R_MAX + rr], 1);
        if (hh != tt && ((bm[tt >> 5] >> (tt & 31)) & 1u))
            atomicAdd(&g_counts[__ldg(&g_node_slot[tt]) * R_MAX + rr], 1);
    };

    bool vec_ok = ((E & 3) == 0);
    if (vec_ok) {
        int quads = E >> 2;
        const int4* h4 = (const int4*)heads;
        const int4* t4 = (const int4*)tails;
        const int4* r4 = (const int4*)types;
        for (int q = blockIdx.x * blockDim.x + threadIdx.x; q < quads;
             q += gridDim.x * blockDim.x) {
            int4 h = h4[q], t = t4[q], r = r4[q];
            proc(h.x, t.x, r.x);
            proc(h.y, t.y, r.y);
            proc(h.z, t.z, r.z);
            proc(h.w, t.w, r.w);
        }
    } else {
        for (int e = blockIdx.x * blockDim.x + threadIdx.x; e < E;
             e += gridDim.x * blockDim.x) {
            proc(heads[e], tails[e], types[e]);
        }
    }

    __syncthreads();
    for (int i = threadIdx.x; i < R; i += blockDim.x) {
        int v = hist[i];
        if (v) atomicAdd(&g_relcnt[i], v);
    }
}

// ---------------------------------------------------------------------------
// K4: one block (256 thr) per query; latency-optimized.
//  - ballot compaction (deterministic) of ~64 nonzero relations
//  - gather: 8 warp-row-groups x float2/lane -> ~8 fully-unrollable loads/thr
//  - MLP input-split across all 256 threads: W1 4x33, W2 8x8, W3 16x2, W4 shfl
// ---------------------------------------------------------------------------
__global__ void __launch_bounds__(256) k_gate(const float* __restrict__ rel_emb,
                                              const int* __restrict__ query_rels,
                                              const int* __restrict__ query_entities,
                                              const float* __restrict__ W1, const float* __restrict__ b1,
                                              const float* __restrict__ W2, const float* __restrict__ b2,
                                              const float* __restrict__ W3, const float* __restrict__ b3,
                                              const float* __restrict__ W4, const float* __restrict__ b4,
                                              float* __restrict__ out,
                                              int R, int D, int E,
                                              const int* __restrict__ num_nodes_ptr,
                                              int n_default) {
    int b = blockIdx.x;
    int t = threadIdx.x;                 // 0..255
    int lane = t & 31;
    int wid  = t >> 5;                   // 0..7

    __shared__ float s_val[R_MAX];
    __shared__ int   s_idx[R_MAX];
    __shared__ int   s_wcnt[8], s_woff[8];
    __shared__ int   s_nnz;
    __shared__ float s_part[8][64];
    __shared__ float s_p1[4][64];
    __shared__ float s_p2[8][32];
    __shared__ float s_p3[16][16];
    __shared__ float s_x[132];
    __shared__ float s_h1[64];
    __shared__ float s_h2[32];
    __shared__ float s_g[16];
    __shared__ float s_wsum[8];
    __shared__ float s_deg;

    int qe = query_entities[b];
    int qr = query_rels[b];
    const float* emb = rel_emb + (size_t)b * (size_t)R_MAX * 64;

    // early independent loads (overlap with count-row latency)
    float qv = 0.f;
    if (t < 64) qv = __ldg(&emb[qr * 64 + t]);
    float rc = (t == 0) ? (float)__ldg(&g_relcnt[qr]) : 0.f;

    int slot = g_node_slot[qe];
    const int* cnt_row = &g_counts[slot * R_MAX];
    float c0 = (float)cnt_row[t];
    float c1 = (float)cnt_row[t + 256];

    // degree reduction (fixed order)
    float part = c0 + c1;
    #pragma unroll
    for (int off = 16; off > 0; off >>= 1)
        part += __shfl_xor_sync(0xffffffffu, part, off);
    if (lane == 0) s_wsum[wid] = part;

    // ---- deterministic compaction, round 0: r = t ----
    bool p0 = (c0 != 0.f);
    unsigned m0 = __ballot_sync(0xffffffffu, p0);
    int wp0 = __popc(m0 & ((1u << lane) - 1u));
    if (lane == 0) s_wcnt[wid] = __popc(m0);
    __syncthreads();
    if (t == 0) {
        int o = 0;
        #pragma unroll
        for (int w = 0; w < 8; w++) { s_woff[w] = o; o += s_wcnt[w]; }
        s_nnz = o;
        float d = 0.f;
        #pragma unroll
        for (int w = 0; w < 8; w++) d += s_wsum[w];
        s_deg = d;
    }
    __syncthreads();
    if (p0) { int p = s_woff[wid] + wp0; s_idx[p] = t; s_val[p] = c0; }
    int base0 = s_nnz;
    __syncthreads();

    // ---- round 1: r = 256 + t ----
    bool p1 = (c1 != 0.f);
    unsigned m1 = __ballot_sync(0xffffffffu, p1);
    int wp1 = __popc(m1 & ((1u << lane) - 1u));
    if (lane == 0) s_wcnt[wid] = __popc(m1);
    __syncthreads();
    if (t == 0) {
        int o = base0;
        #pragma unroll
        for (int w = 0; w < 8; w++) { s_woff[w] = o; o += s_wcnt[w]; }
        s_nnz = o;
    }
    __syncthreads();
    if (p1) { int p = s_woff[wid] + wp1; s_idx[p] = 256 + t; s_val[p] = c1; }
    __syncthreads();

    int nnz = s_nnz;
    float deg = s_deg;
    float inv = 1.0f / fmaxf(deg, 1.0f);

    // ---- gather: warp wid handles rows wid, wid+8, ...; lane -> 2 dims ----
    {
        float ax = 0.f, ay = 0.f;
        #pragma unroll 8
        for (int i = wid; i < nnz; i += 8) {
            float v = s_val[i];
            float2 d = __ldg((const float2*)(emb + s_idx[i] * 64) + lane);
            ax += v * d.x;
            ay += v * d.y;
        }
        s_part[wid][lane * 2]     = ax;
        s_part[wid][lane * 2 + 1] = ay;
    }
    __syncthreads();

    if (t < 64) {
        float a = 0.f;
        #pragma unroll
        for (int w = 0; w < 8; w++) a += s_part[w][t];
        s_x[t]      = qv;
        s_x[64 + t] = a * inv;
    }
    if (t == 0) {
        float Ef   = (float)E;
        float freq = fminf(rc / Ef, 1.0f);
        float degn = fminf(deg / Ef, 1.0f);
        int   N    = num_nodes_ptr ? *num_nodes_ptr : n_default;
        float density = fminf(Ef / ((float)N * (float)N), 1.0f);
        s_x[128 + 0] = freq;
        s_x[128 + 1] = degn;
        s_x[128 + 2] = freq;
        s_x[128 + 3] = density;
    }
    __syncthreads();

    // ---- W1: 132 -> 64, 4-way i-split (33 each) over 256 threads ----
    {
        int jj = t & 63, g = t >> 6;
        float p = 0.f;
        #pragma unroll
        for (int k = 0; k < 33; k++) {
            int i = g * 33 + k;
            p += s_x[i] * __ldg(&W1[i * 64 + jj]);
        }
        s_p1[g][jj] = p;
    }
    __syncthreads();
    if (t < 64)
        s_h1[t] = fmaxf(__ldg(&b1[t]) + s_p1[0][t] + s_p1[1][t] + s_p1[2][t] + s_p1[3][t], 0.f);
    __syncthreads();

    // ---- W2: 64 -> 32, 8-way i-split (8 each) ----
    {
        int o = t & 31, g = t >> 5;
        float p = 0.f;
        #pragma unroll
        for (int k = 0; k < 8; k++) {
            int i = g * 8 + k;
            p += s_h1[i] * __ldg(&W2[i * 32 + o]);
        }
        s_p2[g][o] = p;
    }
    __syncthreads();
    if (t < 32) {
        float a = __ldg(&b2[t]);
        #pragma unroll
        for (int w = 0; w < 8; w++) a += s_p2[w][t];
        s_h2[t] = fmaxf(a, 0.f);
    }
    __syncthreads();

    // ---- W3: 32 -> 16, 16-way i-split (2 each) ----
    {
        int o = t & 15, g = t >> 4;
        int i0 = 2 * g, i1 = 2 * g + 1;
        s_p3[g][o] = s_h2[i0] * __ldg(&W3[i0 * 16 + o]) + s_h2[i1] * __ldg(&W3[i1 * 16 + o]);
    }
    __syncthreads();
    if (t < 16) {
        float a = __ldg(&b3[t]);
        #pragma unroll
        for (int w = 0; w < 16; w++) a += s_p3[w][t];
        s_g[t] = fmaxf(a, 0.f);
    }
    __syncthreads();

    // ---- W4: 16 -> 1 via warp shuffle in warp 0 ----
    if (t < 32) {
        float v = (t < 16) ? s_g[t] * __ldg(&W4[t]) : 0.f;
        #pragma unroll
        for (int off = 8; off > 0; off >>= 1)
            v += __shfl_xor_sync(0xffffffffu, v, off);
        if (t == 0) out[b] = 1.0f / (1.0f + expf(-(v + __ldg(&b4[0]))));
    }
}

// ---------------------------------------------------------------------------
// Host launcher (graph-capturable: kernel launches only, default stream)
// ---------------------------------------------------------------------------
extern "C" void kernel_launch(void* const* d_in, const int* in_sizes, int n_in,
                              void* d_out, int out_size) {
    const float* rel_emb    = (const float*)d_in[0];
    const int*   qrels      = (const int*)d_in[1];
    const int*   qents      = (const int*)d_in[2];
    const int*   edge_index = (const int*)d_in[3];
    const int*   edge_type  = (const int*)d_in[4];

    int B = in_sizes[1];
    int E = in_sizes[4];

    int i = 5;
    const int* num_nodes_ptr = nullptr;
    while (i < n_in && in_sizes[i] == 1) {
        if (num_nodes_ptr == nullptr) num_nodes_ptr = (const int*)d_in[i];
        i++;
    }
    const float* W1 = (const float*)d_in[i + 0];
    const float* b1 = (const float*)d_in[i + 1];
    const float* W2 = (const float*)d_in[i + 2];
    const float* b2 = (const float*)d_in[i + 3];
    const float* W3 = (const float*)d_in[i + 4];
    const float* b3 = (const float*)d_in[i + 5];
    const float* W4 = (const float*)d_in[i + 6];
    const float* b4 = (const float*)d_in[i + 7];

    int D = in_sizes[i + 1];             // 64
    int R = in_sizes[0] / (B * D);       // 512

    k_init_scatter<<<1 + (B_MAX * R_MAX) / 256, 256>>>(qents, B);
    k_scan<<<1184, 256>>>(edge_index, edge_index + E, edge_type, E, R);
    k_gate<<<B, 256>>>(rel_emb, qrels, qents,
                       W1, b1, W2, b2, W3, b3, W4, b4,
                       (float*)d_out, R, D, E, num_nodes_ptr, 100000);
}

// round 16
// speedup vs baseline: 1.9835x; 1.0099x over previous
#include <cuda_runtime.h>
#include <math.h>

// ---------------------------------------------------------------------------
// Problem shape (fixed): B=256, R=512, D=64, N=100000, E=3200000
// ---------------------------------------------------------------------------

#define R_MAX      512
#define B_MAX      256
#define NODE_WORDS 4096          // bitmap capacity: 131072 node ids
#define SLOT_CAP   131072

__device__ int      g_node_slot[SLOT_CAP];
__device__ unsigned g_bitmap[NODE_WORDS];
__device__ int      g_counts[B_MAX * R_MAX];
__device__ int      g_relcnt[R_MAX];

// ---------------------------------------------------------------------------
// K1 (fused init+scatter, vectorized): block 0 clears bitmap/relcnt (int4)
// then scatters query entities; blocks 1..128 clear counts via int4 stores.
// ---------------------------------------------------------------------------
__global__ void k_init_scatter(const int* __restrict__ query_entities, int B) {
    if (blockIdx.x == 0) {
        int4 z4 = make_int4(0, 0, 0, 0);
        int4* bm4 = (int4*)g_bitmap;              // 4096 words = 1024 int4
        for (int i = threadIdx.x; i < NODE_WORDS / 4; i += 256) bm4[i] = z4;
        int4* rc4 = (int4*)g_relcnt;              // 512 words = 128 int4
        if (threadIdx.x < R_MAX / 4) rc4[threadIdx.x] = z4;
        __syncthreads();
        int b = threadIdx.x;
        int e = (b < B) ? query_entities[b] : -1;
        if (b < B) g_node_slot[e] = 0x7fffffff;
        __syncthreads();
        if (b < B) {
            atomicOr(&g_bitmap[e >> 5], 1u << (e & 31));
            atomicMin(&g_node_slot[e], b);
        }
    } else {
        // blocks 1..128: 128 * 256 threads * int4 = 131072 ints = counts
        int i = (blockIdx.x - 1) * 256 + threadIdx.x;
        ((int4*)g_counts)[i] = make_int4(0, 0, 0, 0);
    }
}

// ---------------------------------------------------------------------------
// K3: streaming edge scan (DRAM-bound, unchanged)
// ---------------------------------------------------------------------------
__global__ void __launch_bounds__(256) k_scan(const int* __restrict__ heads,
                                              const int* __restrict__ tails,
                                              const int* __restrict__ types,
                                              int E, int R) {
    __shared__ unsigned bm[NODE_WORDS];
    __shared__ int hist[R_MAX];
    for (int i = threadIdx.x; i < NODE_WORDS; i += blockDim.x) bm[i] = g_bitmap[i];
    for (int i = threadIdx.x; i < R_MAX;      i += blockDim.x) hist[i] = 0;
    __syncthreads();

    auto proc = [&](int hh, int tt, int rr) {
        atomicAdd(&hist[rr], 1);
        if ((bm[hh >> 5] >> (hh & 31)) & 1u)
            atomicAdd(&g_counts[__ldg(&g_node_slot[hh]) * R_MAX + rr], 1);
        if (hh != tt && ((bm[tt >> 5] >> (tt & 31)) & 1u))
            atomicAdd(&g_counts[__ldg(&g_node_slot[tt]) * R_MAX + rr], 1);
    };

    bool vec_ok = ((E & 3) == 0);
    if (vec_ok) {
        int quads = E >> 2;
        const int4* h4 = (const int4*)heads;
        const int4* t4 = (const int4*)tails;
        const int4* r4 = (const int4*)types;
        for (int q = blockIdx.x * blockDim.x + threadIdx.x; q < quads;
             q += gridDim.x * blockDim.x) {
            int4 h = h4[q], t = t4[q], r = r4[q];
            proc(h.x, t.x, r.x);
            proc(h.y, t.y, r.y);
            proc(h.z, t.z, r.z);
            proc(h.w, t.w, r.w);
        }
    } else {
        for (int e = blockIdx.x * blockDim.x + threadIdx.x; e < E;
             e += gridDim.x * blockDim.x) {
            proc(heads[e], tails[e], types[e]);
        }
    }

    __syncthreads();
    for (int i = threadIdx.x; i < R; i += blockDim.x) {
        int v = hist[i];
        if (v) atomicAdd(&g_relcnt[i], v);
    }
}

// ---------------------------------------------------------------------------
// K4: one block (256 thr) per query; latency-optimized.
//  - SINGLE-PASS ballot compaction (both halves before first barrier; 16
//    ordered segments) of ~64 nonzero relations
//  - gather: 8 warp-row-groups x float2/lane -> ~8 fully-unrollable loads/thr
//  - MLP input-split across all 256 threads: W1 4x33, W2 8x8, W3 16x2, W4 shfl
// ---------------------------------------------------------------------------
__global__ void __launch_bounds__(256) k_gate(const float* __restrict__ rel_emb,
                                              const int* __restrict__ query_rels,
                                              const int* __restrict__ query_entities,
                                              const float* __restrict__ W1, const float* __restrict__ b1,
                                              const float* __restrict__ W2, const float* __restrict__ b2,
                                              const float* __restrict__ W3, const float* __restrict__ b3,
                                              const float* __restrict__ W4, const float* __restrict__ b4,
                                              float* __restrict__ out,
                                              int R, int D, int E,
                                              const int* __restrict__ num_nodes_ptr,
                                              int n_default) {
    int b = blockIdx.x;
    int t = threadIdx.x;                 // 0..255
    int lane = t & 31;
    int wid  = t >> 5;                   // 0..7

    __shared__ float s_val[R_MAX];
    __shared__ int   s_idx[R_MAX];
    __shared__ int   s_wcnt0[8], s_wcnt1[8];
    __shared__ int   s_woff0[8], s_woff1[8];
    __shared__ int   s_nnz;
    __shared__ float s_part[8][64];
    __shared__ float s_p1[4][64];
    __shared__ float s_p2[8][32];
    __shared__ float s_p3[16][16];
    __shared__ float s_x[132];
    __shared__ float s_h1[64];
    __shared__ float s_h2[32];
    __shared__ float s_g[16];
    __shared__ float s_wsum[8];
    __shared__ float s_deg;

    int qe = query_entities[b];
    int qr = query_rels[b];
    const float* emb = rel_emb + (size_t)b * (size_t)R_MAX * 64;

    // early independent loads (overlap with count-row latency)
    float qv = 0.f;
    if (t < 64) qv = __ldg(&emb[qr * 64 + t]);
    float rc = (t == 0) ? (float)__ldg(&g_relcnt[qr]) : 0.f;

    int slot = g_node_slot[qe];
    const int* cnt_row = &g_counts[slot * R_MAX];
    float c0 = (float)cnt_row[t];
    float c1 = (float)cnt_row[t + 256];

    // degree reduction (fixed order)
    float part = c0 + c1;
    #pragma unroll
    for (int off = 16; off > 0; off >>= 1)
        part += __shfl_xor_sync(0xffffffffu, part, off);
    if (lane == 0) s_wsum[wid] = part;

    // ---- single-pass deterministic compaction (both halves) ----
    bool p0 = (c0 != 0.f);
    bool p1 = (c1 != 0.f);
    unsigned m0 = __ballot_sync(0xffffffffu, p0);
    unsigned m1 = __ballot_sync(0xffffffffu, p1);
    int wp0 = __popc(m0 & ((1u << lane) - 1u));
    int wp1 = __popc(m1 & ((1u << lane) - 1u));
    if (lane == 0) { s_wcnt0[wid] = __popc(m0); s_wcnt1[wid] = __popc(m1); }
    __syncthreads();
    if (t == 0) {
        int o = 0;
        #pragma unroll
        for (int w = 0; w < 8; w++) { s_woff0[w] = o; o += s_wcnt0[w]; }
        #pragma unroll
        for (int w = 0; w < 8; w++) { s_woff1[w] = o; o += s_wcnt1[w]; }
        s_nnz = o;
        float d = 0.f;
        #pragma unroll
        for (int w = 0; w < 8; w++) d += s_wsum[w];
        s_deg = d;
    }
    __syncthreads();
    if (p0) { int p = s_woff0[wid] + wp0; s_idx[p] = t;       s_val[p] = c0; }
    if (p1) { int p = s_woff1[wid] + wp1; s_idx[p] = 256 + t; s_val[p] = c1; }
    __syncthreads();

    int nnz = s_nnz;
    float deg = s_deg;
    float inv = 1.0f / fmaxf(deg, 1.0f);

    // ---- gather: warp wid handles rows wid, wid+8, ...; lane -> 2 dims ----
    {
        float ax = 0.f, ay = 0.f;
        #pragma unroll 8
        for (int i = wid; i < nnz; i += 8) {
            float v = s_val[i];
            float2 d = __ldg((const float2*)(emb + s_idx[i] * 64) + lane);
            ax += v * d.x;
            ay += v * d.y;
        }
        s_part[wid][lane * 2]     = ax;
        s_part[wid][lane * 2 + 1] = ay;
    }
    __syncthreads();

    if (t < 64) {
        float a = 0.f;
        #pragma unroll
        for (int w = 0; w < 8; w++) a += s_part[w][t];
        s_x[t]      = qv;
        s_x[64 + t] = a * inv;
    }
    if (t == 0) {
        float Ef   = (float)E;
        float freq = fminf(rc / Ef, 1.0f);
        float degn = fminf(deg / Ef, 1.0f);
        int   N    = num_nodes_ptr ? *num_nodes_ptr : n_default;
        float density = fminf(Ef / ((float)N * (float)N), 1.0f);
        s_x[128 + 0] = freq;
        s_x[128 + 1] = degn;
        s_x[128 + 2] = freq;
        s_x[128 + 3] = density;
    }
    __syncthreads();

    // ---- W1: 132 -> 64, 4-way i-split (33 each) over 256 threads ----
    {
        int jj = t & 63, g = t >> 6;
        float p = 0.f;
        #pragma unroll
        for (int k = 0; k < 33; k++) {
            int i = g * 33 + k;
            p += s_x[i] * __ldg(&W1[i * 64 + jj]);
        }
        s_p1[g][jj] = p;
    }
    __syncthreads();
    if (t < 64)
        s_h1[t] = fmaxf(__ldg(&b1[t]) + s_p1[0][t] + s_p1[1][t] + s_p1[2][t] + s_p1[3][t], 0.f);
    __syncthreads();

    // ---- W2: 64 -> 32, 8-way i-split (8 each) ----
    {
        int o = t & 31, g = t >> 5;
        float p = 0.f;
        #pragma unroll
        for (int k = 0; k < 8; k++) {
            int i = g * 8 + k;
            p += s_h1[i] * __ldg(&W2[i * 32 + o]);
        }
        s_p2[g][o] = p;
    }
    __syncthreads();
    if (t < 32) {
        float a = __ldg(&b2[t]);
        #pragma unroll
        for (int w = 0; w < 8; w++) a += s_p2[w][t];
        s_h2[t] = fmaxf(a, 0.f);
    }
    __syncthreads();

    // ---- W3: 32 -> 16, 16-way i-split (2 each) ----
    {
        int o = t & 15, g = t >> 4;
        int i0 = 2 * g, i1 = 2 * g + 1;
        s_p3[g][o] = s_h2[i0] * __ldg(&W3[i0 * 16 + o]) + s_h2[i1] * __ldg(&W3[i1 * 16 + o]);
    }
    __syncthreads();
    if (t < 16) {
        float a = __ldg(&b3[t]);
        #pragma unroll
        for (int w = 0; w < 16; w++) a += s_p3[w][t];
        s_g[t] = fmaxf(a, 0.f);
    }
    __syncthreads();

    // ---- W4: 16 -> 1 via warp shuffle in warp 0 ----
    if (t < 32) {
        float v = (t < 16) ? s_g[t] * __ldg(&W4[t]) : 0.f;
        #pragma unroll
        for (int off = 8; off > 0; off >>= 1)
            v += __shfl_xor_sync(0xffffffffu, v, off);
        if (t == 0) out[b] = 1.0f / (1.0f + expf(-(v + __ldg(&b4[0]))));
    }
}

// ---------------------------------------------------------------------------
// Host launcher (graph-capturable: kernel launches only, default stream)
// ---------------------------------------------------------------------------
extern "C" void kernel_launch(void* const* d_in, const int* in_sizes, int n_in,
                              void* d_out, int out_size) {
    const float* rel_emb    = (const float*)d_in[0];
    const int*   qrels      = (const int*)d_in[1];
    const int*   qents      = (const int*)d_in[2];
    const int*   edge_index = (const int*)d_in[3];
    const int*   edge_type  = (const int*)d_in[4];

    int B = in_sizes[1];
    int E = in_sizes[4];

    int i = 5;
    const int* num_nodes_ptr = nullptr;
    while (i < n_in && in_sizes[i] == 1) {
        if (num_nodes_ptr == nullptr) num_nodes_ptr = (const int*)d_in[i];
        i++;
    }
    const float* W1 = (const float*)d_in[i + 0];
    const float* b1 = (const float*)d_in[i + 1];
    const float* W2 = (const float*)d_in[i + 2];
    const float* b2 = (const float*)d_in[i + 3];
    const float* W3 = (const float*)d_in[i + 4];
    const float* b3 = (const float*)d_in[i + 5];
    const float* W4 = (const float*)d_in[i + 6];
    const float* b4 = (const float*)d_in[i + 7];

    int D = in_sizes[i + 1];             // 64
    int R = in_sizes[0] / (B * D);       // 512

    // 1 scatter block + 128 int4-clear blocks (128*256*4 = 131072 ints)
    k_init_scatter<<<129, 256>>>(qents, B);
    k_scan<<<1184, 256>>>(edge_index, edge_index + E, edge_type, E, R);
    k_gate<<<B, 256>>>(rel_emb, qrels, qents,
                       W1, b1, W2, b2, W3, b3, W4, b4,
                       (float*)d_out, R, D, E, num_nodes_ptr, 100000);
}